// round 11
// baseline (speedup 1.0000x reference)
#include <cuda_runtime.h>
#include <cuda_bf16.h>
#include <math.h>
#include <stdint.h>

#define BB 32
#define SS 4096

// ---------------- device scratch ----------------
__device__ float g_q[BB * 512];
__device__ float g_scores[2 * BB * SS];   // two slabs (n0 halves), summed in softmax
__device__ __align__(16) unsigned short g_Wt_hi[512 * 512];  // W^T [a][e], bf16 hi
__device__ __align__(16) unsigned short g_Wt_lo[512 * 512];  // W^T [a][e], bf16 lo

// ---------------- smem layout (per CTA) ----------------
// A: 2 bufs x 8KB  (64 rows x 128B: hi k32 64B | lo k32 64B)
// B: 3 bufs x 32KB (256 rows x 128B: hi k32 64B | lo k32 64B)
// reduction buffer reuses the A region after the mainloop.
#define OFF_A    0
#define OFF_B    16384
#define SMEM_DYN 114688   // 16K + 96K; x2 CTAs = 224KB <= 228KB/SM

// ---------------- asm helpers ----------------
__device__ __forceinline__ uint32_t smem_to_u32(const void* p) {
    uint32_t a;
    asm("{ .reg .u64 t; cvta.to.shared.u64 t, %1; cvt.u32.u64 %0, t; }" : "=r"(a) : "l"(p));
    return a;
}
__device__ __forceinline__ void ldsm4(uint32_t* r, uint32_t addr) {
    asm volatile("ldmatrix.sync.aligned.m8n8.x4.shared.b16 {%0,%1,%2,%3}, [%4];"
                 : "=r"(r[0]), "=r"(r[1]), "=r"(r[2]), "=r"(r[3]) : "r"(addr));
}
__device__ __forceinline__ void mma16816(float* c, const uint32_t* a, uint32_t b0, uint32_t b1) {
    asm volatile("mma.sync.aligned.m16n8k16.row.col.f32.bf16.bf16.f32 "
                 "{%0,%1,%2,%3}, {%4,%5,%6,%7}, {%8,%9}, {%0,%1,%2,%3};"
                 : "+f"(c[0]), "+f"(c[1]), "+f"(c[2]), "+f"(c[3])
                 : "r"(a[0]), "r"(a[1]), "r"(a[2]), "r"(a[3]), "r"(b0), "r"(b1));
}
__device__ __forceinline__ void cp_async16(uint32_t dst, const void* src) {
    asm volatile("{ .reg .u64 g; cvta.to.global.u64 g, %1; "
                 "cp.async.cg.shared.global [%0], [g], 16; }"
                 :: "r"(dst), "l"(src) : "memory");
}
#define CP_COMMIT() asm volatile("cp.async.commit_group;" ::: "memory")
#define CP_WAIT0()  asm volatile("cp.async.wait_group 0;" ::: "memory")
#define CP_WAIT1()  asm volatile("cp.async.wait_group 1;" ::: "memory")

// r = 1/(e^{2x}+1); z = fma(acc, C, qc). ex2 via MUFU, rcp via magic+2 Newton.
#define TANH_C 2.885390081777927f
__device__ __forceinline__ float sig_rcp(float acc, float qc) {
    float z = fmaf(acc, TANH_C, qc);
    z = fminf(z, 126.0f);
    float e2;
    asm("ex2.approx.f32 %0, %1;" : "=f"(e2) : "f"(z));
    float d = e2 + 1.0f;
    float y = __int_as_float(0x7EF311C3 - __float_as_int(d));
    y = y * fmaf(-d, y, 2.0f);
    y = y * fmaf(-d, y, 2.0f);
    return y;
}

// ---------------------------------------------------------------------------
// prep: wsplit (blocks 0..511) | query (512..543)
// ---------------------------------------------------------------------------
__global__ void prep_kernel(const float* __restrict__ W_s,
                            const float* __restrict__ h,
                            const float* __restrict__ W_h) {
    __shared__ float hs[512];
    const int bid = blockIdx.x;
    const int t = threadIdx.x;
    if (bid < 512) {
        float w = W_s[bid * 512 + t];
        uint32_t u = __float_as_uint(w);
        g_Wt_hi[(size_t)t * 512 + bid] = (unsigned short)(u >> 16);
        float lo = w - __uint_as_float(u & 0xffff0000u);
        __nv_bfloat16 lb = __float2bfloat16(lo);
        g_Wt_lo[(size_t)t * 512 + bid] = *(unsigned short*)&lb;
    } else {
        const int b = bid - 512;
        hs[t] = h[b * 512 + t];
        __syncthreads();
        float acc = 0.f;
#pragma unroll 8
        for (int e = 0; e < 512; e++)
            acc = fmaf(hs[e], W_h[e * 512 + t], acc);
        g_q[b * 512 + t] = acc;
    }
}

// ---------------------------------------------------------------------------
// Score kernel: CTA = (m-tile 64 tok, n-tile 256 attn, b). 256 thr, 8 warps,
// 2 CTAs/SM. Warp (mw=w&1, nw=w>>1): tile m32 x n64.
// K: 16 chunks of 32. A: depth-2 ring. B: depth-3 ring, fill(c+2) issued at
// start of chunk c, wait_group(1) at end -> fill latency fully hidden.
// One __syncthreads per chunk. Partial scores -> own slab, no atomics.
// ---------------------------------------------------------------------------
__global__ __launch_bounds__(256, 2)
void score_mma_kernel(const float* __restrict__ enc,
                      const float* __restrict__ v) {
    extern __shared__ __align__(128) char sm[];
    const uint32_t sb = smem_to_u32(sm);
    const int t = threadIdx.x;
    const int w = t >> 5, lid = t & 31;
    const int mw = w & 1, nw = w >> 1;
    const int mtile = blockIdx.x;          // 0..63
    const int nhalf = blockIdx.y;          // 0 or 1
    const int n0 = nhalf * 256;
    const int b = blockIdx.z;

    const float* encb = enc + ((size_t)b * SS + (size_t)mtile * 64) * 512;

    float acc[2][8][4];
#pragma unroll
    for (int mg = 0; mg < 2; mg++)
#pragma unroll
        for (int j = 0; j < 8; j++)
#pragma unroll
            for (int e = 0; e < 4; e++) acc[mg][j][e] = 0.f;

    const int am = t >> 2, akq = t & 3;    // A roles: row 0..63, k-quad 0..3

// B chunk: 256 rows x (hi 64B | lo 64B); 2048 16B-chunks, 8 per thread
#define ISSUE_B(s_, slot_) do {                                               \
    const uint32_t bb = sb + OFF_B + (slot_) * 32768;                         \
    const int k0_ = (s_) * 32;                                                \
    _Pragma("unroll")                                                         \
    for (int i_ = 0; i_ < 8; i_++) {                                          \
        int idx_ = t + i_ * 256;                                              \
        int r_ = idx_ >> 3;                                                   \
        int cc_ = idx_ & 7;                                                   \
        const unsigned short* src_ =                                          \
            (cc_ < 4 ? g_Wt_hi : g_Wt_lo) + (size_t)(n0 + r_) * 512 + k0_ + (cc_ & 3) * 8; \
        cp_async16(bb + r_ * 128 + ((cc_ ^ (r_ & 7)) << 4), src_);            \
    } } while (0)

// A chunk: row am, 8 fp32 at k = s*32 + akq*8
#define LOAD_A(s_, af_) do {                                                  \
    const float* p_ = encb + (size_t)am * 512 + (s_) * 32 + akq * 8;          \
    af_[0] = *(const float4*)(p_);                                            \
    af_[1] = *(const float4*)(p_ + 4);                                        \
    } while (0)

#define STORE_A(buf_, af_) do {                                               \
    char* ab_ = sm + OFF_A + (buf_) * 8192;                                   \
    float4 f0 = af_[0], f1 = af_[1];                                          \
    uint32_t x0 = __float_as_uint(f0.x), x1 = __float_as_uint(f0.y);          \
    uint32_t x2 = __float_as_uint(f0.z), x3 = __float_as_uint(f0.w);          \
    uint32_t x4 = __float_as_uint(f1.x), x5 = __float_as_uint(f1.y);          \
    uint32_t x6 = __float_as_uint(f1.z), x7 = __float_as_uint(f1.w);          \
    uint4 hv;                                                                 \
    hv.x = __byte_perm(x0, x1, 0x7632);                                       \
    hv.y = __byte_perm(x2, x3, 0x7632);                                       \
    hv.z = __byte_perm(x4, x5, 0x7632);                                       \
    hv.w = __byte_perm(x6, x7, 0x7632);                                       \
    float l0 = f0.x - __uint_as_float(x0 & 0xffff0000u);                      \
    float l1 = f0.y - __uint_as_float(x1 & 0xffff0000u);                      \
    float l2 = f0.z - __uint_as_float(x2 & 0xffff0000u);                      \
    float l3 = f0.w - __uint_as_float(x3 & 0xffff0000u);                      \
    float l4 = f1.x - __uint_as_float(x4 & 0xffff0000u);                      \
    float l5 = f1.y - __uint_as_float(x5 & 0xffff0000u);                      \
    float l6 = f1.z - __uint_as_float(x6 & 0xffff0000u);                      \
    float l7 = f1.w - __uint_as_float(x7 & 0xffff0000u);                      \
    uint4 lv;                                                                 \
    asm("cvt.rn.satfinite.bf16x2.f32 %0, %1, %2;" : "=r"(lv.x) : "f"(l1), "f"(l0)); \
    asm("cvt.rn.satfinite.bf16x2.f32 %0, %1, %2;" : "=r"(lv.y) : "f"(l3), "f"(l2)); \
    asm("cvt.rn.satfinite.bf16x2.f32 %0, %1, %2;" : "=r"(lv.z) : "f"(l5), "f"(l4)); \
    asm("cvt.rn.satfinite.bf16x2.f32 %0, %1, %2;" : "=r"(lv.w) : "f"(l7), "f"(l6)); \
    uint32_t offh_ = am * 128 + ((akq ^ (am & 7)) << 4);                      \
    *(uint4*)(ab_ + offh_) = hv;                                              \
    *(uint4*)(ab_ + (offh_ ^ 64)) = lv;                                       \
    } while (0)

    const int rA = mw * 32 + ((lid >> 3) & 1) * 8 + (lid & 7);  // 0..47
    const int rAx = rA & 7;
    const int cAadd = lid >> 4;
    const int rB = nw * 64 + ((lid >> 4) & 1) * 8 + (lid & 7);
    const int cBadd = (lid >> 3) & 1;

    // ---- prologue: B(0),B(1) in flight; A(0) in smem; A(1) in regs --------
    ISSUE_B(0, 0);
    CP_COMMIT();
    ISSUE_B(1, 1);
    CP_COMMIT();
    float4 af[2];
    LOAD_A(0, af);
    STORE_A(0, af);
    LOAD_A(1, af);
    CP_WAIT1();               // B(0) complete (B(1) may be outstanding)
    __syncthreads();

#pragma unroll 1
    for (int c = 0; c < 16; c++) {
        const int slot = c % 3;
        const int abuf = c & 1;
        // fill for chunk c+2 into the slot drained in chunk c-1
        if (c < 14) { ISSUE_B(c + 2, (c + 2) % 3); CP_COMMIT(); }

        const uint32_t ab = sb + OFF_A + abuf * 8192;
        const uint32_t bb = sb + OFF_B + slot * 32768;

#pragma unroll
        for (int kk = 0; kk < 2; kk++) {
            const int cA = kk * 2 + cAadd;
            const uint32_t a0off = (uint32_t)rA * 128 + (uint32_t)((cA ^ rAx) << 4);
            const uint32_t a1off = a0off + 16 * 128;      // (rA+16)&7 == rA&7
            const int cB = kk * 2 + cBadd;
            uint32_t boff[4];
            uint32_t bm[4][4];
#pragma unroll
            for (int j = 0; j < 4; j++) {
                int r = rB + j * 16;
                boff[j] = (uint32_t)r * 128 + (uint32_t)((cB ^ (r & 7)) << 4);
                ldsm4(bm[j], bb + boff[j]);
            }
            uint32_t ah0[4], ah1[4], al[4];
            ldsm4(ah0, ab + a0off);
            ldsm4(ah1, ab + a1off);

            // pass 1: Ah*Bh
#pragma unroll
            for (int j = 0; j < 4; j++) {
                mma16816(acc[0][2 * j],     ah0, bm[j][0], bm[j][1]);
                mma16816(acc[0][2 * j + 1], ah0, bm[j][2], bm[j][3]);
                mma16816(acc[1][2 * j],     ah1, bm[j][0], bm[j][1]);
                mma16816(acc[1][2 * j + 1], ah1, bm[j][2], bm[j][3]);
            }
            // pass 2: Al*Bh  (lo = hi addr ^ 64)
            ldsm4(al, ab + (a0off ^ 64));
#pragma unroll
            for (int j = 0; j < 4; j++) {
                mma16816(acc[0][2 * j],     al, bm[j][0], bm[j][1]);
                mma16816(acc[0][2 * j + 1], al, bm[j][2], bm[j][3]);
            }
            ldsm4(al, ab + (a1off ^ 64));
#pragma unroll
            for (int j = 0; j < 4; j++) {
                mma16816(acc[1][2 * j],     al, bm[j][0], bm[j][1]);
                mma16816(acc[1][2 * j + 1], al, bm[j][2], bm[j][3]);
            }
            // pass 3: Ah*Bl
#pragma unroll
            for (int j = 0; j < 4; j++) ldsm4(bm[j], bb + (boff[j] ^ 64));
#pragma unroll
            for (int j = 0; j < 4; j++) {
                mma16816(acc[0][2 * j],     ah0, bm[j][0], bm[j][1]);
                mma16816(acc[0][2 * j + 1], ah0, bm[j][2], bm[j][3]);
                mma16816(acc[1][2 * j],     ah1, bm[j][0], bm[j][1]);
                mma16816(acc[1][2 * j + 1], ah1, bm[j][2], bm[j][3]);
            }
        }

        if (c < 15) {
            // B(c+1) complete; the c+2 fill may remain outstanding (except tail)
            if (c < 14) { CP_WAIT1(); } else { CP_WAIT0(); }
            STORE_A(abuf ^ 1, af);   // A(c+1) into slot drained in chunk c-1
            if (c < 14) LOAD_A(c + 2, af);
            __syncthreads();         // publishes A(c+1) + B(c+1)
        }
    }

    // ---- epilogue: score = Sv - 2 * sum(v * 1/(e^{2x}+1)) ----------------
    float qc[8][2], vv[8][2];
    float Sv = 0.f;
#pragma unroll
    for (int j = 0; j < 8; j++) {
        const int c = n0 + nw * 64 + j * 8 + 2 * (lid & 3);
        float2 q2 = *(const float2*)(g_q + b * 512 + c);
        float2 v2 = *(const float2*)(v + c);
        qc[j][0] = q2.x * TANH_C;
        qc[j][1] = q2.y * TANH_C;
        vv[j][0] = v2.x;
        vv[j][1] = v2.y;
        Sv += v2.x + v2.y;
    }

    float part[2][2] = {{0.f, 0.f}, {0.f, 0.f}};
#pragma unroll
    for (int mg = 0; mg < 2; mg++) {
#pragma unroll
        for (int j = 0; j < 8; j++) {
            part[mg][0] = fmaf(vv[j][0], sig_rcp(acc[mg][j][0], qc[j][0]), part[mg][0]);
            part[mg][0] = fmaf(vv[j][1], sig_rcp(acc[mg][j][1], qc[j][1]), part[mg][0]);
            part[mg][1] = fmaf(vv[j][0], sig_rcp(acc[mg][j][2], qc[j][0]), part[mg][1]);
            part[mg][1] = fmaf(vv[j][1], sig_rcp(acc[mg][j][3], qc[j][1]), part[mg][1]);
        }
    }

    // reduction buffer reuses the (dead) A ring region
    float* red = (float*)(sm + OFF_A);     // [4 nw][64 rows]
    __syncthreads();
#pragma unroll
    for (int mg = 0; mg < 2; mg++)
#pragma unroll
        for (int hf = 0; hf < 2; hf++) {
            float p = fmaf(-2.0f, part[mg][hf], Sv);
            p += __shfl_xor_sync(0xffffffffu, p, 1);
            p += __shfl_xor_sync(0xffffffffu, p, 2);
            if ((lid & 3) == 0)
                red[nw * 64 + mw * 32 + mg * 16 + hf * 8 + (lid >> 2)] = p;
        }
    __syncthreads();
    if (t < 64) {
        float p = red[t] + red[64 + t] + red[128 + t] + red[192 + t];
        g_scores[((size_t)nhalf * BB + b) * SS + mtile * 64 + t] = p;  // own slab
    }
}

// ---------------------------------------------------------------------------
// Softmax over S per batch row (sums the two slabs, applies mask)
// ---------------------------------------------------------------------------
__global__ void softmax_kernel(const int* __restrict__ mask,
                               float* __restrict__ out_attn) {
    const int b = blockIdx.x;
    const int t = threadIdx.x;   // 256
    __shared__ float red[256];
    const float* sc0 = g_scores + (size_t)b * SS;
    const float* sc1 = g_scores + ((size_t)BB + b) * SS;
    const int* mk = mask + b * SS;

    float vals[16];
    float m = -INFINITY;
#pragma unroll
    for (int i = 0; i < 16; i++) {
        int s = t + i * 256;
        vals[i] = (mk[s] != 0) ? -1e9f : (sc0[s] + sc1[s]);
        m = fmaxf(m, vals[i]);
    }
    red[t] = m;
    __syncthreads();
    for (int o = 128; o > 0; o >>= 1) {
        if (t < o) red[t] = fmaxf(red[t], red[t + o]);
        __syncthreads();
    }
    m = red[0];
    __syncthreads();

    float sum = 0.f;
#pragma unroll
    for (int i = 0; i < 16; i++) {
        vals[i] = expf(vals[i] - m);
        sum += vals[i];
    }
    red[t] = sum;
    __syncthreads();
    for (int o = 128; o > 0; o >>= 1) {
        if (t < o) red[t] += red[t + o];
        __syncthreads();
    }
    const float inv = 1.f / red[0];
#pragma unroll
    for (int i = 0; i < 16; i++)
        out_attn[b * SS + t + i * 256] = vals[i] * inv;
}

// ---------------------------------------------------------------------------
// ctx[b,e] = sum_s attn[b,s] * enc[b,s,e]   (grid 64 x 32, 64-token chunks)
// ---------------------------------------------------------------------------
__global__ void ctx_kernel(const float* __restrict__ enc_out,
                           const float* __restrict__ attn,
                           float* __restrict__ ctx) {
    const int b = blockIdx.y;
    const int sch = blockIdx.x;
    const int e4 = threadIdx.x * 4;
    const float* ap = attn + b * SS + sch * 64;
    const float* ep = enc_out + ((size_t)b * SS + (size_t)sch * 64) * 512 + e4;

    float4 acc0 = make_float4(0.f, 0.f, 0.f, 0.f);
    float4 acc1 = make_float4(0.f, 0.f, 0.f, 0.f);
#pragma unroll 8
    for (int s = 0; s < 64; s += 2) {
        float a0 = __ldg(&ap[s]);
        float a1 = __ldg(&ap[s + 1]);
        float4 x0 = *(const float4*)(ep + (size_t)s * 512);
        float4 x1 = *(const float4*)(ep + (size_t)(s + 1) * 512);
        acc0.x = fmaf(a0, x0.x, acc0.x);
        acc0.y = fmaf(a0, x0.y, acc0.y);
        acc0.z = fmaf(a0, x0.z, acc0.z);
        acc0.w = fmaf(a0, x0.w, acc0.w);
        acc1.x = fmaf(a1, x1.x, acc1.x);
        acc1.y = fmaf(a1, x1.y, acc1.y);
        acc1.z = fmaf(a1, x1.z, acc1.z);
        acc1.w = fmaf(a1, x1.w, acc1.w);
    }
    atomicAdd(&ctx[b * 512 + e4 + 0], acc0.x + acc1.x);
    atomicAdd(&ctx[b * 512 + e4 + 1], acc0.y + acc1.y);
    atomicAdd(&ctx[b * 512 + e4 + 2], acc0.z + acc1.z);
    atomicAdd(&ctx[b * 512 + e4 + 3], acc0.w + acc1.w);
}

// ---------------------------------------------------------------------------
extern "C" void kernel_launch(void* const* d_in, const int* in_sizes, int n_in,
                              void* d_out, int out_size) {
    const float* h    = (const float*)d_in[0];
    const float* enc  = (const float*)d_in[1];
    const int*   mask = (const int*)d_in[2];
    const float* W_h  = (const float*)d_in[3];
    const float* W_s  = (const float*)d_in[4];
    const float* v    = (const float*)d_in[5];

    float* out  = (float*)d_out;
    float* ctx  = out;                 // [32, 512]
    float* attn = out + BB * 512;      // [32, 4096]

    static int attr_done = 0;
    if (!attr_done) {
        cudaFuncSetAttribute(score_mma_kernel,
                             cudaFuncAttributeMaxDynamicSharedMemorySize, SMEM_DYN);
        attr_done = 1;
    }

    cudaMemsetAsync(ctx, 0, BB * 512 * sizeof(float));
    prep_kernel<<<544, 512>>>(W_s, h, W_h);
    score_mma_kernel<<<dim3(64, 2, 32), 256, SMEM_DYN>>>(enc, v);
    softmax_kernel<<<BB, 256>>>(mask, attn);
    ctx_kernel<<<dim3(64, 32), 128>>>(enc, attn, ctx);
}

// round 13
// speedup vs baseline: 1.3413x; 1.3413x over previous
#include <cuda_runtime.h>
#include <cuda_fp16.h>
#include <math.h>
#include <stdint.h>

#define BB 32
#define SS 4096

// ---------------- device scratch ----------------
__device__ float g_q[BB * 512];
__device__ float g_scores[BB * SS];
__device__ __align__(16) unsigned short g_Wt[512 * 512];  // W^T [a][e], fp16

// ---------------- smem layout (per CTA) ----------------
// A: 2 bufs x 16KB (hi 8KB: 64 rows x 128B (k64), lo 8KB) = 32KB
// B: 2 bufs x 32KB (fp16: 256 rows x 128B (k64))          = 64KB
#define OFF_A    0
#define OFF_B    32768
#define OFF_RED  98304    // 4 x 64 f32 = 1KB
#define SMEM_DYN 99328

// ---------------- asm helpers ----------------
__device__ __forceinline__ uint32_t smem_to_u32(const void* p) {
    uint32_t a;
    asm("{ .reg .u64 t; cvta.to.shared.u64 t, %1; cvt.u32.u64 %0, t; }" : "=r"(a) : "l"(p));
    return a;
}
__device__ __forceinline__ void ldsm4(uint32_t* r, uint32_t addr) {
    asm volatile("ldmatrix.sync.aligned.m8n8.x4.shared.b16 {%0,%1,%2,%3}, [%4];"
                 : "=r"(r[0]), "=r"(r[1]), "=r"(r[2]), "=r"(r[3]) : "r"(addr));
}
__device__ __forceinline__ void mma16816(float* c, const uint32_t* a, uint32_t b0, uint32_t b1) {
    asm volatile("mma.sync.aligned.m16n8k16.row.col.f32.f16.f16.f32 "
                 "{%0,%1,%2,%3}, {%4,%5,%6,%7}, {%8,%9}, {%0,%1,%2,%3};"
                 : "+f"(c[0]), "+f"(c[1]), "+f"(c[2]), "+f"(c[3])
                 : "r"(a[0]), "r"(a[1]), "r"(a[2]), "r"(a[3]), "r"(b0), "r"(b1));
}
__device__ __forceinline__ void cp_async16(uint32_t dst, const void* src) {
    asm volatile("{ .reg .u64 g; cvta.to.global.u64 g, %1; "
                 "cp.async.cg.shared.global [%0], [g], 16; }"
                 :: "r"(dst), "l"(src) : "memory");
}
#define CP_COMMIT() asm volatile("cp.async.commit_group;" ::: "memory")
#define CP_WAIT0()  asm volatile("cp.async.wait_group 0;" ::: "memory")

// fp16x2 pack with round-to-nearest, plus exact fp32 residuals
__device__ __forceinline__ uint32_t cvt_f16x2(float lo, float hi) {
    uint32_t r;
    asm("cvt.rn.f16x2.f32 %0, %1, %2;" : "=r"(r) : "f"(hi), "f"(lo));
    return r;
}

// r = 1/(e^{2x}+1); z = fma(acc, C, qc). ex2 via MUFU, rcp via magic+3 Newton.
#define TANH_C 2.885390081777927f
__device__ __forceinline__ float sig_rcp(float acc, float qc) {
    float z = fmaf(acc, TANH_C, qc);
    z = fminf(z, 126.0f);
    float e2;
    asm("ex2.approx.f32 %0, %1;" : "=f"(e2) : "f"(z));
    float d = e2 + 1.0f;
    float y = __int_as_float(0x7EF311C3 - __float_as_int(d));
    y = y * fmaf(-d, y, 2.0f);
    y = y * fmaf(-d, y, 2.0f);
    y = y * fmaf(-d, y, 2.0f);
    return y;
}

// ---------------------------------------------------------------------------
// prep: W->fp16 transpose (blocks 0..511) | query (512..543) | zero (544..607)
// ---------------------------------------------------------------------------
__global__ void prep_kernel(const float* __restrict__ W_s,
                            const float* __restrict__ h,
                            const float* __restrict__ W_h) {
    __shared__ float hs[512];
    const int bid = blockIdx.x;
    const int t = threadIdx.x;
    if (bid < 512) {
        float w = W_s[bid * 512 + t];
        __half wh = __float2half_rn(w);
        g_Wt[(size_t)t * 512 + bid] = *(unsigned short*)&wh;
    } else if (bid < 544) {
        const int b = bid - 512;
        hs[t] = h[b * 512 + t];
        __syncthreads();
        float acc = 0.f;
#pragma unroll 8
        for (int e = 0; e < 512; e++)
            acc = fmaf(hs[e], W_h[e * 512 + t], acc);
        g_q[b * 512 + t] = acc;
    } else {
        ((float4*)g_scores)[(bid - 544) * 512 + t] = make_float4(0.f, 0.f, 0.f, 0.f);
    }
}

// ---------------------------------------------------------------------------
// Score kernel: CTA = (m-tile 64 tok, n-tile 256 attn, b). 256 thr, 8 warps,
// 2 CTAs/SM. Warp (mw=w&1, nw=w>>1): tile m32 x n64.
// K: 8 chunks of 64; A(hi+lo fp16) and B(fp16) depth-2 rings; fill(c+1)
// issued at iteration start; ONE __syncthreads per chunk.
// 2-pass: D = Ah*B + Al*B = (near-exact A) * fp16(W).
// ---------------------------------------------------------------------------
__global__ __launch_bounds__(256, 2)
void score_mma_kernel(const float* __restrict__ enc,
                      const float* __restrict__ v) {
    extern __shared__ __align__(128) char sm[];
    const uint32_t sb = smem_to_u32(sm);
    const int t = threadIdx.x;
    const int w = t >> 5, lid = t & 31;
    const int mw = w & 1, nw = w >> 1;
    const int mtile = blockIdx.x;          // 0..63
    const int n0 = blockIdx.y * 256;       // 0 or 256
    const int b = blockIdx.z;

    const float* encb = enc + ((size_t)b * SS + (size_t)mtile * 64) * 512;

    float acc[2][8][4];
#pragma unroll
    for (int mg = 0; mg < 2; mg++)
#pragma unroll
        for (int j = 0; j < 8; j++)
#pragma unroll
            for (int e = 0; e < 4; e++) acc[mg][j][e] = 0.f;

    const int am = t >> 2, akq = t & 3;    // A roles: row 0..63, k-quad (16 fl)

// B chunk (fp16, k64): 256 rows x 128B = 2048 16B-chunks, 8 per thread
#define ISSUE_B(s_, buf_) do {                                                \
    const uint32_t bb = sb + OFF_B + (buf_) * 32768;                          \
    const int k0_ = (s_) * 64;                                                \
    _Pragma("unroll")                                                         \
    for (int i_ = 0; i_ < 8; i_++) {                                          \
        int idx_ = t + i_ * 256;                                              \
        int r_ = idx_ >> 3;                                                   \
        int cc_ = idx_ & 7;                                                   \
        const unsigned short* src_ =                                          \
            g_Wt + (size_t)(n0 + r_) * 512 + k0_ + cc_ * 8;                   \
        cp_async16(bb + r_ * 128 + ((cc_ ^ (r_ & 7)) << 4), src_);            \
    } } while (0)

// A chunk (k64): row am, 16 fp32 at k = s*64 + akq*16
#define LOAD_A(s_, af_) do {                                                  \
    const float* p_ = encb + (size_t)am * 512 + (s_) * 64 + akq * 16;         \
    af_[0] = *(const float4*)(p_);                                            \
    af_[1] = *(const float4*)(p_ + 4);                                        \
    af_[2] = *(const float4*)(p_ + 8);                                        \
    af_[3] = *(const float4*)(p_ + 12);                                       \
    } while (0)

#define STORE_A(buf_, af_) do {                                               \
    char* ab_ = sm + OFF_A + (buf_) * 16384;                                  \
    _Pragma("unroll")                                                         \
    for (int c_ = 0; c_ < 2; c_++) {                                          \
        float4 f0 = af_[2 * c_], f1 = af_[2 * c_ + 1];                        \
        uint4 hv;                                                             \
        hv.x = cvt_f16x2(f0.x, f0.y);                                         \
        hv.y = cvt_f16x2(f0.z, f0.w);                                         \
        hv.z = cvt_f16x2(f1.x, f1.y);                                         \
        hv.w = cvt_f16x2(f1.z, f1.w);                                         \
        float2 r0 = __half22float2(*(__half2*)&hv.x);                         \
        float2 r1 = __half22float2(*(__half2*)&hv.y);                         \
        float2 r2 = __half22float2(*(__half2*)&hv.z);                         \
        float2 r3 = __half22float2(*(__half2*)&hv.w);                         \
        uint4 lv;                                                             \
        lv.x = cvt_f16x2(f0.x - r0.x, f0.y - r0.y);                           \
        lv.y = cvt_f16x2(f0.z - r1.x, f0.w - r1.y);                           \
        lv.z = cvt_f16x2(f1.x - r2.x, f1.y - r2.y);                           \
        lv.w = cvt_f16x2(f1.z - r3.x, f1.w - r3.y);                           \
        int cc_ = akq * 2 + c_;                                               \
        uint32_t off_ = am * 128 + ((cc_ ^ (am & 7)) << 4);                   \
        *(uint4*)(ab_ + off_) = hv;                                           \
        *(uint4*)(ab_ + 8192 + off_) = lv;                                    \
    } } while (0)

    const int rA = mw * 32 + ((lid >> 3) & 1) * 8 + (lid & 7);  // 0..47
    const int rAx = rA & 7;
    const int cAadd = lid >> 4;
    const int rB = nw * 64 + ((lid >> 4) & 1) * 8 + (lid & 7);
    const int cBadd = (lid >> 3) & 1;

    // ---- prologue: chunk 0 in smem, chunk-1 A in regs ----------------------
    ISSUE_B(0, 0);
    CP_COMMIT();
    float4 af[4];
    LOAD_A(0, af);
    STORE_A(0, af);
    LOAD_A(1, af);            // chunk 1 A staged in regs
    CP_WAIT0();               // B(0) complete
    __syncthreads();

#pragma unroll 1
    for (int c = 0; c < 8; c++) {
        const int buf = c & 1;
        // kick off next B fill FIRST: overlaps this chunk's MMAs.
        if (c < 7) { ISSUE_B(c + 1, buf ^ 1); CP_COMMIT(); }

        const uint32_t abh = sb + OFF_A + buf * 16384;
        const uint32_t abl = abh + 8192;
        const uint32_t bb = sb + OFF_B + buf * 32768;

#pragma unroll
        for (int kk = 0; kk < 4; kk++) {
            const int cA = kk * 2 + cAadd;
            const uint32_t a0off = (uint32_t)rA * 128 + (uint32_t)((cA ^ rAx) << 4);
            const uint32_t a1off = a0off + 16 * 128;      // (rA+16)&7 == rA&7
            const int cB = kk * 2 + cBadd;
            uint32_t boff[4];
            uint32_t bm[4][4];
#pragma unroll
            for (int j = 0; j < 4; j++) {
                int r = rB + j * 16;
                boff[j] = (uint32_t)r * 128 + (uint32_t)((cB ^ (r & 7)) << 4);
                ldsm4(bm[j], bb + boff[j]);
            }
            uint32_t ah0[4], ah1[4], al[4];
            ldsm4(ah0, abh + a0off);
            ldsm4(ah1, abh + a1off);

            // pass 1: Ah*B
#pragma unroll
            for (int j = 0; j < 4; j++) {
                mma16816(acc[0][2 * j],     ah0, bm[j][0], bm[j][1]);
                mma16816(acc[0][2 * j + 1], ah0, bm[j][2], bm[j][3]);
                mma16816(acc[1][2 * j],     ah1, bm[j][0], bm[j][1]);
                mma16816(acc[1][2 * j + 1], ah1, bm[j][2], bm[j][3]);
            }
            // pass 2: Al*B
            ldsm4(al, abl + a0off);
#pragma unroll
            for (int j = 0; j < 4; j++) {
                mma16816(acc[0][2 * j],     al, bm[j][0], bm[j][1]);
                mma16816(acc[0][2 * j + 1], al, bm[j][2], bm[j][3]);
            }
            ldsm4(al, abl + a1off);
#pragma unroll
            for (int j = 0; j < 4; j++) {
                mma16816(acc[1][2 * j],     al, bm[j][0], bm[j][1]);
                mma16816(acc[1][2 * j + 1], al, bm[j][2], bm[j][3]);
            }
        }

        if (c < 7) {
            CP_WAIT0();             // B(c+1) fill complete (overlapped above)
            STORE_A(buf ^ 1, af);   // A(c+1) into buffer drained in chunk c-1
            if (c < 6) LOAD_A(c + 2, af);
            __syncthreads();        // ONE barrier: publishes A(c+1) + B(c+1)
        }
    }

    // ---- epilogue: score = Sv - 2 * sum(v * 1/(e^{2x}+1)) ----------------
    float qc[8][2], vv[8][2];
    float Sv = 0.f;
#pragma unroll
    for (int j = 0; j < 8; j++) {
        const int c = n0 + nw * 64 + j * 8 + 2 * (lid & 3);
        float2 q2 = *(const float2*)(g_q + b * 512 + c);
        float2 v2 = *(const float2*)(v + c);
        qc[j][0] = q2.x * TANH_C;
        qc[j][1] = q2.y * TANH_C;
        vv[j][0] = v2.x;
        vv[j][1] = v2.y;
        Sv += v2.x + v2.y;
    }

    float part[2][2] = {{0.f, 0.f}, {0.f, 0.f}};
#pragma unroll
    for (int mg = 0; mg < 2; mg++) {
#pragma unroll
        for (int j = 0; j < 8; j++) {
            part[mg][0] = fmaf(vv[j][0], sig_rcp(acc[mg][j][0], qc[j][0]), part[mg][0]);
            part[mg][0] = fmaf(vv[j][1], sig_rcp(acc[mg][j][1], qc[j][1]), part[mg][0]);
            part[mg][1] = fmaf(vv[j][0], sig_rcp(acc[mg][j][2], qc[j][0]), part[mg][1]);
            part[mg][1] = fmaf(vv[j][1], sig_rcp(acc[mg][j][3], qc[j][1]), part[mg][1]);
        }
    }

    float* red = (float*)(sm + OFF_RED);   // [4 nw][64 rows]
    __syncthreads();
#pragma unroll
    for (int mg = 0; mg < 2; mg++)
#pragma unroll
        for (int hf = 0; hf < 2; hf++) {
            float p = fmaf(-2.0f, part[mg][hf], Sv);
            p += __shfl_xor_sync(0xffffffffu, p, 1);
            p += __shfl_xor_sync(0xffffffffu, p, 2);
            if ((lid & 3) == 0)
                red[nw * 64 + mw * 32 + mg * 16 + hf * 8 + (lid >> 2)] = p;
        }
    __syncthreads();
    if (t < 64) {
        float p = red[t] + red[64 + t] + red[128 + t] + red[192 + t];
        atomicAdd(&g_scores[b * SS + mtile * 64 + t], p);
    }
}

// ---------------------------------------------------------------------------
// Softmax over S per batch row (applies mask here)
// ---------------------------------------------------------------------------
__global__ void softmax_kernel(const int* __restrict__ mask,
                               float* __restrict__ out_attn) {
    const int b = blockIdx.x;
    const int t = threadIdx.x;   // 256
    __shared__ float red[256];
    const float* sc = g_scores + b * SS;
    const int* mk = mask + b * SS;

    float vals[16];
    float m = -INFINITY;
#pragma unroll
    for (int i = 0; i < 16; i++) {
        int s = t + i * 256;
        vals[i] = (mk[s] != 0) ? -1e9f : sc[s];
        m = fmaxf(m, vals[i]);
    }
    red[t] = m;
    __syncthreads();
    for (int o = 128; o > 0; o >>= 1) {
        if (t < o) red[t] = fmaxf(red[t], red[t + o]);
        __syncthreads();
    }
    m = red[0];
    __syncthreads();

    float sum = 0.f;
#pragma unroll
    for (int i = 0; i < 16; i++) {
        vals[i] = expf(vals[i] - m);
        sum += vals[i];
    }
    red[t] = sum;
    __syncthreads();
    for (int o = 128; o > 0; o >>= 1) {
        if (t < o) red[t] += red[t + o];
        __syncthreads();
    }
    const float inv = 1.f / red[0];
#pragma unroll
    for (int i = 0; i < 16; i++)
        out_attn[b * SS + t + i * 256] = vals[i] * inv;
}

// ---------------------------------------------------------------------------
// ctx[b,e] = sum_s attn[b,s] * enc[b,s,e]
// ---------------------------------------------------------------------------
__global__ void ctx_kernel(const float* __restrict__ enc_out,
                           const float* __restrict__ attn,
                           float* __restrict__ ctx) {
    const int b = blockIdx.y;
    const int sch = blockIdx.x;
    const int e4 = threadIdx.x * 4;
    const float* ap = attn + b * SS + sch * 128;
    const float* ep = enc_out + ((size_t)b * SS + (size_t)sch * 128) * 512 + e4;

    float4 acc0 = make_float4(0.f, 0.f, 0.f, 0.f);
    float4 acc1 = make_float4(0.f, 0.f, 0.f, 0.f);
#pragma unroll 8
    for (int s = 0; s < 128; s += 2) {
        float a0 = __ldg(&ap[s]);
        float a1 = __ldg(&ap[s + 1]);
        float4 x0 = *(const float4*)(ep + (size_t)s * 512);
        float4 x1 = *(const float4*)(ep + (size_t)(s + 1) * 512);
        acc0.x = fmaf(a0, x0.x, acc0.x);
        acc0.y = fmaf(a0, x0.y, acc0.y);
        acc0.z = fmaf(a0, x0.z, acc0.z);
        acc0.w = fmaf(a0, x0.w, acc0.w);
        acc1.x = fmaf(a1, x1.x, acc1.x);
        acc1.y = fmaf(a1, x1.y, acc1.y);
        acc1.z = fmaf(a1, x1.z, acc1.z);
        acc1.w = fmaf(a1, x1.w, acc1.w);
    }
    atomicAdd(&ctx[b * 512 + e4 + 0], acc0.x + acc1.x);
    atomicAdd(&ctx[b * 512 + e4 + 1], acc0.y + acc1.y);
    atomicAdd(&ctx[b * 512 + e4 + 2], acc0.z + acc1.z);
    atomicAdd(&ctx[b * 512 + e4 + 3], acc0.w + acc1.w);
}

// ---------------------------------------------------------------------------
extern "C" void kernel_launch(void* const* d_in, const int* in_sizes, int n_in,
                              void* d_out, int out_size) {
    const float* h    = (const float*)d_in[0];
    const float* enc  = (const float*)d_in[1];
    const int*   mask = (const int*)d_in[2];
    const float* W_h  = (const float*)d_in[3];
    const float* W_s  = (const float*)d_in[4];
    const float* v    = (const float*)d_in[5];

    float* out  = (float*)d_out;
    float* ctx  = out;                 // [32, 512]
    float* attn = out + BB * 512;      // [32, 4096]

    static int attr_done = 0;
    if (!attr_done) {
        cudaFuncSetAttribute(score_mma_kernel,
                             cudaFuncAttributeMaxDynamicSharedMemorySize, SMEM_DYN);
        attr_done = 1;
    }

    cudaMemsetAsync(ctx, 0, BB * 512 * sizeof(float));
    prep_kernel<<<608, 512>>>(W_s, h, W_h);
    score_mma_kernel<<<dim3(64, 2, 32), 256, SMEM_DYN>>>(enc, v);
    softmax_kernel<<<BB, 256>>>(mask, attn);
    ctx_kernel<<<dim3(32, 32), 128>>>(enc, attn, ctx);
}

// round 14
// speedup vs baseline: 1.8482x; 1.3779x over previous
#include <cuda_runtime.h>
#include <cuda_fp16.h>
#include <math.h>
#include <stdint.h>

#define BB 32
#define SS 4096

// ---------------- device scratch ----------------
__device__ float g_q[BB * 512];
__device__ float g_scores[BB * SS];
__device__ __align__(16) unsigned short g_Wt[512 * 512];  // W^T [a][e], fp16

// ---------------- smem layout (per CTA) ----------------
// A: 2 bufs x 8KB  (fp16: 64 rows x 128B (k64))
// B: 2 bufs x 32KB (fp16: 256 rows x 128B (k64))
#define OFF_A    0
#define OFF_B    16384
#define OFF_RED  81920    // 4 x 64 f32 = 1KB
#define SMEM_DYN 82944

// ---------------- asm helpers ----------------
__device__ __forceinline__ uint32_t smem_to_u32(const void* p) {
    uint32_t a;
    asm("{ .reg .u64 t; cvta.to.shared.u64 t, %1; cvt.u32.u64 %0, t; }" : "=r"(a) : "l"(p));
    return a;
}
__device__ __forceinline__ void ldsm4(uint32_t* r, uint32_t addr) {
    asm volatile("ldmatrix.sync.aligned.m8n8.x4.shared.b16 {%0,%1,%2,%3}, [%4];"
                 : "=r"(r[0]), "=r"(r[1]), "=r"(r[2]), "=r"(r[3]) : "r"(addr));
}
__device__ __forceinline__ void mma16816(float* c, const uint32_t* a, uint32_t b0, uint32_t b1) {
    asm volatile("mma.sync.aligned.m16n8k16.row.col.f32.f16.f16.f32 "
                 "{%0,%1,%2,%3}, {%4,%5,%6,%7}, {%8,%9}, {%0,%1,%2,%3};"
                 : "+f"(c[0]), "+f"(c[1]), "+f"(c[2]), "+f"(c[3])
                 : "r"(a[0]), "r"(a[1]), "r"(a[2]), "r"(a[3]), "r"(b0), "r"(b1));
}
__device__ __forceinline__ void cp_async16(uint32_t dst, const void* src) {
    asm volatile("{ .reg .u64 g; cvta.to.global.u64 g, %1; "
                 "cp.async.cg.shared.global [%0], [g], 16; }"
                 :: "r"(dst), "l"(src) : "memory");
}
#define CP_COMMIT() asm volatile("cp.async.commit_group;" ::: "memory")
#define CP_WAIT0()  asm volatile("cp.async.wait_group 0;" ::: "memory")

// fp16x2 pack with round-to-nearest
__device__ __forceinline__ uint32_t cvt_f16x2(float lo, float hi) {
    uint32_t r;
    asm("cvt.rn.f16x2.f32 %0, %1, %2;" : "=r"(r) : "f"(hi), "f"(lo));
    return r;
}

// r = 1/(e^{2x}+1); z = fma(acc, C, qc). ex2 via MUFU, rcp via magic+3 Newton.
#define TANH_C 2.885390081777927f
__device__ __forceinline__ float sig_rcp(float acc, float qc) {
    float z = fmaf(acc, TANH_C, qc);
    z = fminf(z, 126.0f);
    float e2;
    asm("ex2.approx.f32 %0, %1;" : "=f"(e2) : "f"(z));
    float d = e2 + 1.0f;
    float y = __int_as_float(0x7EF311C3 - __float_as_int(d));
    y = y * fmaf(-d, y, 2.0f);
    y = y * fmaf(-d, y, 2.0f);
    y = y * fmaf(-d, y, 2.0f);
    return y;
}

// ---------------------------------------------------------------------------
// prep: W->fp16 transpose (blocks 0..511) | query (512..543) | zero (544..607)
// ---------------------------------------------------------------------------
__global__ void prep_kernel(const float* __restrict__ W_s,
                            const float* __restrict__ h,
                            const float* __restrict__ W_h) {
    __shared__ float hs[512];
    const int bid = blockIdx.x;
    const int t = threadIdx.x;
    if (bid < 512) {
        float w = W_s[bid * 512 + t];
        __half wh = __float2half_rn(w);
        g_Wt[(size_t)t * 512 + bid] = *(unsigned short*)&wh;
    } else if (bid < 544) {
        const int b = bid - 512;
        hs[t] = h[b * 512 + t];
        __syncthreads();
        float acc = 0.f;
#pragma unroll 8
        for (int e = 0; e < 512; e++)
            acc = fmaf(hs[e], W_h[e * 512 + t], acc);
        g_q[b * 512 + t] = acc;
    } else {
        ((float4*)g_scores)[(bid - 544) * 512 + t] = make_float4(0.f, 0.f, 0.f, 0.f);
    }
}

// ---------------------------------------------------------------------------
// Score kernel: CTA = (m-tile 64 tok, n-tile 256 attn, b). 256 thr, 8 warps,
// 2 CTAs/SM. Warp (mw=w&1, nw=w>>1): tile m32 x n64.
// K: 8 chunks of 64; A(fp16) and B(fp16) depth-2 rings; fill(c+1) issued
// at iteration start; ONE __syncthreads per chunk. Single pass: D = A*B.
// ---------------------------------------------------------------------------
__global__ __launch_bounds__(256, 2)
void score_mma_kernel(const float* __restrict__ enc,
                      const float* __restrict__ v) {
    extern __shared__ __align__(128) char sm[];
    const uint32_t sb = smem_to_u32(sm);
    const int t = threadIdx.x;
    const int w = t >> 5, lid = t & 31;
    const int mw = w & 1, nw = w >> 1;
    const int mtile = blockIdx.x;          // 0..63
    const int n0 = blockIdx.y * 256;       // 0 or 256
    const int b = blockIdx.z;

    const float* encb = enc + ((size_t)b * SS + (size_t)mtile * 64) * 512;

    float acc[2][8][4];
#pragma unroll
    for (int mg = 0; mg < 2; mg++)
#pragma unroll
        for (int j = 0; j < 8; j++)
#pragma unroll
            for (int e = 0; e < 4; e++) acc[mg][j][e] = 0.f;

    const int am = t >> 2, akq = t & 3;    // A roles: row 0..63, k-quad (16 fl)

// B chunk (fp16, k64): 256 rows x 128B = 2048 16B-chunks, 8 per thread
#define ISSUE_B(s_, buf_) do {                                                \
    const uint32_t bb = sb + OFF_B + (buf_) * 32768;                          \
    const int k0_ = (s_) * 64;                                                \
    _Pragma("unroll")                                                         \
    for (int i_ = 0; i_ < 8; i_++) {                                          \
        int idx_ = t + i_ * 256;                                              \
        int r_ = idx_ >> 3;                                                   \
        int cc_ = idx_ & 7;                                                   \
        const unsigned short* src_ =                                          \
            g_Wt + (size_t)(n0 + r_) * 512 + k0_ + cc_ * 8;                   \
        cp_async16(bb + r_ * 128 + ((cc_ ^ (r_ & 7)) << 4), src_);            \
    } } while (0)

// A chunk (k64): row am, 16 fp32 at k = s*64 + akq*16
#define LOAD_A(s_, af_) do {                                                  \
    const float* p_ = encb + (size_t)am * 512 + (s_) * 64 + akq * 16;         \
    af_[0] = *(const float4*)(p_);                                            \
    af_[1] = *(const float4*)(p_ + 4);                                        \
    af_[2] = *(const float4*)(p_ + 8);                                        \
    af_[3] = *(const float4*)(p_ + 12);                                       \
    } while (0)

#define STORE_A(buf_, af_) do {                                               \
    char* ab_ = sm + OFF_A + (buf_) * 8192;                                   \
    _Pragma("unroll")                                                         \
    for (int c_ = 0; c_ < 2; c_++) {                                          \
        float4 f0 = af_[2 * c_], f1 = af_[2 * c_ + 1];                        \
        uint4 hv;                                                             \
        hv.x = cvt_f16x2(f0.x, f0.y);                                         \
        hv.y = cvt_f16x2(f0.z, f0.w);                                         \
        hv.z = cvt_f16x2(f1.x, f1.y);                                         \
        hv.w = cvt_f16x2(f1.z, f1.w);                                         \
        int cc_ = akq * 2 + c_;                                               \
        uint32_t off_ = am * 128 + ((cc_ ^ (am & 7)) << 4);                   \
        *(uint4*)(ab_ + off_) = hv;                                           \
    } } while (0)

    const int rA = mw * 32 + ((lid >> 3) & 1) * 8 + (lid & 7);  // 0..47
    const int rAx = rA & 7;
    const int cAadd = lid >> 4;
    const int rB = nw * 64 + ((lid >> 4) & 1) * 8 + (lid & 7);
    const int cBadd = (lid >> 3) & 1;

    // ---- prologue: chunk 0 in smem, chunk-1 A in regs ----------------------
    ISSUE_B(0, 0);
    CP_COMMIT();
    float4 af[4];
    LOAD_A(0, af);
    STORE_A(0, af);
    LOAD_A(1, af);            // chunk 1 A staged in regs
    CP_WAIT0();               // B(0) complete
    __syncthreads();

#pragma unroll 1
    for (int c = 0; c < 8; c++) {
        const int buf = c & 1;
        // kick off next B fill FIRST: overlaps this chunk's MMAs.
        if (c < 7) { ISSUE_B(c + 1, buf ^ 1); CP_COMMIT(); }

        const uint32_t ab = sb + OFF_A + buf * 8192;
        const uint32_t bb = sb + OFF_B + buf * 32768;

#pragma unroll
        for (int kk = 0; kk < 4; kk++) {
            const int cA = kk * 2 + cAadd;
            const uint32_t a0off = (uint32_t)rA * 128 + (uint32_t)((cA ^ rAx) << 4);
            const uint32_t a1off = a0off + 16 * 128;      // (rA+16)&7 == rA&7
            const int cB = kk * 2 + cBadd;
            uint32_t boff[4];
            uint32_t bm[4][4];
#pragma unroll
            for (int j = 0; j < 4; j++) {
                int r = rB + j * 16;
                boff[j] = (uint32_t)r * 128 + (uint32_t)((cB ^ (r & 7)) << 4);
                ldsm4(bm[j], bb + boff[j]);
            }
            uint32_t ah0[4], ah1[4];
            ldsm4(ah0, ab + a0off);
            ldsm4(ah1, ab + a1off);

#pragma unroll
            for (int j = 0; j < 4; j++) {
                mma16816(acc[0][2 * j],     ah0, bm[j][0], bm[j][1]);
                mma16816(acc[0][2 * j + 1], ah0, bm[j][2], bm[j][3]);
                mma16816(acc[1][2 * j],     ah1, bm[j][0], bm[j][1]);
                mma16816(acc[1][2 * j + 1], ah1, bm[j][2], bm[j][3]);
            }
        }

        if (c < 7) {
            CP_WAIT0();             // B(c+1) fill complete (overlapped above)
            STORE_A(buf ^ 1, af);   // A(c+1) into buffer drained in chunk c-1
            if (c < 6) LOAD_A(c + 2, af);
            __syncthreads();        // ONE barrier: publishes A(c+1) + B(c+1)
        }
    }

    // ---- epilogue: score = Sv - 2 * sum(v * 1/(e^{2x}+1)) ----------------
    float qc[8][2], vv[8][2];
    float Sv = 0.f;
#pragma unroll
    for (int j = 0; j < 8; j++) {
        const int c = n0 + nw * 64 + j * 8 + 2 * (lid & 3);
        float2 q2 = *(const float2*)(g_q + b * 512 + c);
        float2 v2 = *(const float2*)(v + c);
        qc[j][0] = q2.x * TANH_C;
        qc[j][1] = q2.y * TANH_C;
        vv[j][0] = v2.x;
        vv[j][1] = v2.y;
        Sv += v2.x + v2.y;
    }

    float part[2][2] = {{0.f, 0.f}, {0.f, 0.f}};
#pragma unroll
    for (int mg = 0; mg < 2; mg++) {
#pragma unroll
        for (int j = 0; j < 8; j++) {
            part[mg][0] = fmaf(vv[j][0], sig_rcp(acc[mg][j][0], qc[j][0]), part[mg][0]);
            part[mg][0] = fmaf(vv[j][1], sig_rcp(acc[mg][j][1], qc[j][1]), part[mg][0]);
            part[mg][1] = fmaf(vv[j][0], sig_rcp(acc[mg][j][2], qc[j][0]), part[mg][1]);
            part[mg][1] = fmaf(vv[j][1], sig_rcp(acc[mg][j][3], qc[j][1]), part[mg][1]);
        }
    }

    float* red = (float*)(sm + OFF_RED);   // [4 nw][64 rows]
    __syncthreads();
#pragma unroll
    for (int mg = 0; mg < 2; mg++)
#pragma unroll
        for (int hf = 0; hf < 2; hf++) {
            float p = fmaf(-2.0f, part[mg][hf], Sv);
            p += __shfl_xor_sync(0xffffffffu, p, 1);
            p += __shfl_xor_sync(0xffffffffu, p, 2);
            if ((lid & 3) == 0)
                red[nw * 64 + mw * 32 + mg * 16 + hf * 8 + (lid >> 2)] = p;
        }
    __syncthreads();
    if (t < 64) {
        float p = red[t] + red[64 + t] + red[128 + t] + red[192 + t];
        atomicAdd(&g_scores[b * SS + mtile * 64 + t], p);
    }
}

// ---------------------------------------------------------------------------
// Softmax over S per batch row (applies mask here)
// ---------------------------------------------------------------------------
__global__ void softmax_kernel(const int* __restrict__ mask,
                               float* __restrict__ out_attn) {
    const int b = blockIdx.x;
    const int t = threadIdx.x;   // 256
    __shared__ float red[256];
    const float* sc = g_scores + b * SS;
    const int* mk = mask + b * SS;

    float vals[16];
    float m = -INFINITY;
#pragma unroll
    for (int i = 0; i < 16; i++) {
        int s = t + i * 256;
        vals[i] = (mk[s] != 0) ? -1e9f : sc[s];
        m = fmaxf(m, vals[i]);
    }
    red[t] = m;
    __syncthreads();
    for (int o = 128; o > 0; o >>= 1) {
        if (t < o) red[t] = fmaxf(red[t], red[t + o]);
        __syncthreads();
    }
    m = red[0];
    __syncthreads();

    float sum = 0.f;
#pragma unroll
    for (int i = 0; i < 16; i++) {
        vals[i] = expf(vals[i] - m);
        sum += vals[i];
    }
    red[t] = sum;
    __syncthreads();
    for (int o = 128; o > 0; o >>= 1) {
        if (t < o) red[t] += red[t + o];
        __syncthreads();
    }
    const float inv = 1.f / red[0];
#pragma unroll
    for (int i = 0; i < 16; i++)
        out_attn[b * SS + t + i * 256] = vals[i] * inv;
}

// ---------------------------------------------------------------------------
// ctx[b,e] = sum_s attn[b,s] * enc[b,s,e]
// ---------------------------------------------------------------------------
__global__ void ctx_kernel(const float* __restrict__ enc_out,
                           const float* __restrict__ attn,
                           float* __restrict__ ctx) {
    const int b = blockIdx.y;
    const int sch = blockIdx.x;
    const int e4 = threadIdx.x * 4;
    const float* ap = attn + b * SS + sch * 128;
    const float* ep = enc_out + ((size_t)b * SS + (size_t)sch * 128) * 512 + e4;

    float4 acc0 = make_float4(0.f, 0.f, 0.f, 0.f);
    float4 acc1 = make_float4(0.f, 0.f, 0.f, 0.f);
#pragma unroll 8
    for (int s = 0; s < 128; s += 2) {
        float a0 = __ldg(&ap[s]);
        float a1 = __ldg(&ap[s + 1]);
        float4 x0 = *(const float4*)(ep + (size_t)s * 512);
        float4 x1 = *(const float4*)(ep + (size_t)(s + 1) * 512);
        acc0.x = fmaf(a0, x0.x, acc0.x);
        acc0.y = fmaf(a0, x0.y, acc0.y);
        acc0.z = fmaf(a0, x0.z, acc0.z);
        acc0.w = fmaf(a0, x0.w, acc0.w);
        acc1.x = fmaf(a1, x1.x, acc1.x);
        acc1.y = fmaf(a1, x1.y, acc1.y);
        acc1.z = fmaf(a1, x1.z, acc1.z);
        acc1.w = fmaf(a1, x1.w, acc1.w);
    }
    atomicAdd(&ctx[b * 512 + e4 + 0], acc0.x + acc1.x);
    atomicAdd(&ctx[b * 512 + e4 + 1], acc0.y + acc1.y);
    atomicAdd(&ctx[b * 512 + e4 + 2], acc0.z + acc1.z);
    atomicAdd(&ctx[b * 512 + e4 + 3], acc0.w + acc1.w);
}

// ---------------------------------------------------------------------------
extern "C" void kernel_launch(void* const* d_in, const int* in_sizes, int n_in,
                              void* d_out, int out_size) {
    const float* h    = (const float*)d_in[0];
    const float* enc  = (const float*)d_in[1];
    const int*   mask = (const int*)d_in[2];
    const float* W_h  = (const float*)d_in[3];
    const float* W_s  = (const float*)d_in[4];
    const float* v    = (const float*)d_in[5];

    float* out  = (float*)d_out;
    float* ctx  = out;                 // [32, 512]
    float* attn = out + BB * 512;      // [32, 4096]

    static int attr_done = 0;
    if (!attr_done) {
        cudaFuncSetAttribute(score_mma_kernel,
                             cudaFuncAttributeMaxDynamicSharedMemorySize, SMEM_DYN);
        attr_done = 1;
    }

    cudaMemsetAsync(ctx, 0, BB * 512 * sizeof(float));
    prep_kernel<<<608, 512>>>(W_s, h, W_h);
    score_mma_kernel<<<dim3(64, 2, 32), 256, SMEM_DYN>>>(enc, v);
    softmax_kernel<<<BB, 256>>>(mask, attn);
    ctx_kernel<<<dim3(32, 32), 128>>>(enc, attn, ctx);
}

// round 15
// speedup vs baseline: 1.9618x; 1.0615x over previous
#include <cuda_runtime.h>
#include <cuda_fp16.h>
#include <math.h>
#include <stdint.h>

#define BB 32
#define SS 4096

// ---------------- device scratch ----------------
__device__ float g_q[BB * 512];
__device__ float g_scores[BB * SS];
__device__ __align__(16) unsigned short g_Wt[512 * 512];              // W^T [a][e], fp16
__device__ __align__(16) unsigned short g_enc_h[(size_t)BB * SS * 512]; // enc fp16, 134MB

// ---------------- smem layout (per CTA) ----------------
// A: 2 bufs x 16KB (fp16: 128 rows x 128B (k64))
// B: 2 bufs x 16KB (fp16: 128 rows x 128B (k64))
#define OFF_A    0
#define OFF_B    32768
#define OFF_RED  65536    // 2 x 128 f32 = 1KB
#define SMEM_DYN 66560

// ---------------- asm helpers ----------------
__device__ __forceinline__ uint32_t smem_to_u32(const void* p) {
    uint32_t a;
    asm("{ .reg .u64 t; cvta.to.shared.u64 t, %1; cvt.u32.u64 %0, t; }" : "=r"(a) : "l"(p));
    return a;
}
__device__ __forceinline__ void ldsm4(uint32_t* r, uint32_t addr) {
    asm volatile("ldmatrix.sync.aligned.m8n8.x4.shared.b16 {%0,%1,%2,%3}, [%4];"
                 : "=r"(r[0]), "=r"(r[1]), "=r"(r[2]), "=r"(r[3]) : "r"(addr));
}
__device__ __forceinline__ void mma16816(float* c, const uint32_t* a, uint32_t b0, uint32_t b1) {
    asm volatile("mma.sync.aligned.m16n8k16.row.col.f32.f16.f16.f32 "
                 "{%0,%1,%2,%3}, {%4,%5,%6,%7}, {%8,%9}, {%0,%1,%2,%3};"
                 : "+f"(c[0]), "+f"(c[1]), "+f"(c[2]), "+f"(c[3])
                 : "r"(a[0]), "r"(a[1]), "r"(a[2]), "r"(a[3]), "r"(b0), "r"(b1));
}
__device__ __forceinline__ void cp_async16(uint32_t dst, const void* src) {
    asm volatile("{ .reg .u64 g; cvta.to.global.u64 g, %1; "
                 "cp.async.cg.shared.global [%0], [g], 16; }"
                 :: "r"(dst), "l"(src) : "memory");
}
#define CP_COMMIT() asm volatile("cp.async.commit_group;" ::: "memory")
#define CP_WAIT0()  asm volatile("cp.async.wait_group 0;" ::: "memory")

// fp16x2 pack with round-to-nearest
__device__ __forceinline__ uint32_t cvt_f16x2(float lo, float hi) {
    uint32_t r;
    asm("cvt.rn.f16x2.f32 %0, %1, %2;" : "=r"(r) : "f"(hi), "f"(lo));
    return r;
}

// r = 1/(e^{2x}+1); z = fma(acc, C, qc). ex2 via MUFU, rcp via magic+3 Newton.
#define TANH_C 2.885390081777927f
__device__ __forceinline__ float sig_rcp(float acc, float qc) {
    float z = fmaf(acc, TANH_C, qc);
    z = fminf(z, 126.0f);
    float e2;
    asm("ex2.approx.f32 %0, %1;" : "=f"(e2) : "f"(z));
    float d = e2 + 1.0f;
    float y = __int_as_float(0x7EF311C3 - __float_as_int(d));
    y = y * fmaf(-d, y, 2.0f);
    y = y * fmaf(-d, y, 2.0f);
    y = y * fmaf(-d, y, 2.0f);
    return y;
}

// ---------------------------------------------------------------------------
// prep: W->fp16^T (0..511) | query (512..543) | zero scores (544..607) |
//       enc fp32 -> fp16 (608..33375)
// ---------------------------------------------------------------------------
__global__ void prep_kernel(const float* __restrict__ W_s,
                            const float* __restrict__ h,
                            const float* __restrict__ W_h,
                            const float* __restrict__ enc) {
    __shared__ float hs[512];
    const int bid = blockIdx.x;
    const int t = threadIdx.x;
    if (bid >= 608) {                      // enc convert: 4 floats per thread
        size_t i = ((size_t)(bid - 608) * 512 + t) * 4;
        float4 f = *(const float4*)(enc + i);
        uint2 hv;
        hv.x = cvt_f16x2(f.x, f.y);
        hv.y = cvt_f16x2(f.z, f.w);
        *(uint2*)(g_enc_h + i) = hv;
    } else if (bid < 512) {
        float w = W_s[bid * 512 + t];
        __half wh = __float2half_rn(w);
        g_Wt[(size_t)t * 512 + bid] = *(unsigned short*)&wh;
    } else if (bid < 544) {
        const int b = bid - 512;
        hs[t] = h[b * 512 + t];
        __syncthreads();
        float acc = 0.f;
#pragma unroll 8
        for (int e = 0; e < 512; e++)
            acc = fmaf(hs[e], W_h[e * 512 + t], acc);
        g_q[b * 512 + t] = acc;
    } else {
        ((float4*)g_scores)[(bid - 544) * 512 + t] = make_float4(0.f, 0.f, 0.f, 0.f);
    }
}

// ---------------------------------------------------------------------------
// Score kernel: CTA = (n-quarter 128 attn, m-tile 128 tok, b). 256 thr,
// 8 warps (mw=w&3, nw=w>>2): warp tile m32 x n64. 2 CTAs/SM.
// K: 8 chunks of 64; A and B BOTH fp16 via cp.async, depth-2 rings,
// one commit group + ONE __syncthreads per chunk. Single pass: D = A*B.
// ---------------------------------------------------------------------------
__global__ __launch_bounds__(256, 2)
void score_mma_kernel(const float* __restrict__ v) {
    extern __shared__ __align__(128) char sm[];
    const uint32_t sb = smem_to_u32(sm);
    const int t = threadIdx.x;
    const int w = t >> 5, lid = t & 31;
    const int mw = w & 3, nw = w >> 2;
    const int n0 = blockIdx.x * 128;       // nq fastest: 4 CTAs share A in L2
    const int mtile = blockIdx.y;          // 0..31
    const int b = blockIdx.z;

    const unsigned short* encb = g_enc_h + ((size_t)b * SS + (size_t)mtile * 128) * 512;

    float acc[2][8][4];
#pragma unroll
    for (int mg = 0; mg < 2; mg++)
#pragma unroll
        for (int j = 0; j < 8; j++)
#pragma unroll
            for (int e = 0; e < 4; e++) acc[mg][j][e] = 0.f;

// A chunk (fp16, k64): 128 rows x 128B = 1024 16B-chunks, 4 per thread
#define ISSUE_A(s_, buf_) do {                                                \
    const uint32_t aa = sb + OFF_A + (buf_) * 16384;                          \
    const int k0_ = (s_) * 64;                                                \
    _Pragma("unroll")                                                         \
    for (int i_ = 0; i_ < 4; i_++) {                                          \
        int idx_ = t + i_ * 256;                                              \
        int r_ = idx_ >> 3;                                                   \
        int cc_ = idx_ & 7;                                                   \
        cp_async16(aa + r_ * 128 + ((cc_ ^ (r_ & 7)) << 4),                   \
                   encb + (size_t)r_ * 512 + k0_ + cc_ * 8);                  \
    } } while (0)

// B chunk (fp16, k64): 128 rows x 128B = 1024 16B-chunks, 4 per thread
#define ISSUE_B(s_, buf_) do {                                                \
    const uint32_t bb = sb + OFF_B + (buf_) * 16384;                          \
    const int k0_ = (s_) * 64;                                                \
    _Pragma("unroll")                                                         \
    for (int i_ = 0; i_ < 4; i_++) {                                          \
        int idx_ = t + i_ * 256;                                              \
        int r_ = idx_ >> 3;                                                   \
        int cc_ = idx_ & 7;                                                   \
        cp_async16(bb + r_ * 128 + ((cc_ ^ (r_ & 7)) << 4),                   \
                   g_Wt + (size_t)(n0 + r_) * 512 + k0_ + cc_ * 8);           \
    } } while (0)

    const int rA = mw * 32 + ((lid >> 3) & 1) * 8 + (lid & 7);  // 0..127
    const int rAx = rA & 7;
    const int cAadd = lid >> 4;
    const int rB = nw * 64 + ((lid >> 4) & 1) * 8 + (lid & 7);  // 0..127
    const int cBadd = (lid >> 3) & 1;

    // ---- prologue: chunk 0 in flight -------------------------------------
    ISSUE_A(0, 0);
    ISSUE_B(0, 0);
    CP_COMMIT();
    CP_WAIT0();
    __syncthreads();

#pragma unroll 1
    for (int c = 0; c < 8; c++) {
        const int buf = c & 1;
        // fills for chunk c+1 overlap this chunk's MMAs (buffer drained in c-1)
        if (c < 7) { ISSUE_A(c + 1, buf ^ 1); ISSUE_B(c + 1, buf ^ 1); CP_COMMIT(); }

        const uint32_t ab = sb + OFF_A + buf * 16384;
        const uint32_t bb = sb + OFF_B + buf * 16384;

#pragma unroll
        for (int kk = 0; kk < 4; kk++) {
            const int cA = kk * 2 + cAadd;
            const uint32_t a0off = (uint32_t)rA * 128 + (uint32_t)((cA ^ rAx) << 4);
            const uint32_t a1off = a0off + 16 * 128;      // (rA+16)&7 == rA&7
            const int cB = kk * 2 + cBadd;
            uint32_t boff[4];
            uint32_t bm[4][4];
#pragma unroll
            for (int j = 0; j < 4; j++) {
                int r = rB + j * 16;
                boff[j] = (uint32_t)r * 128 + (uint32_t)((cB ^ (r & 7)) << 4);
                ldsm4(bm[j], bb + boff[j]);
            }
            uint32_t ah0[4], ah1[4];
            ldsm4(ah0, ab + a0off);
            ldsm4(ah1, ab + a1off);

#pragma unroll
            for (int j = 0; j < 4; j++) {
                mma16816(acc[0][2 * j],     ah0, bm[j][0], bm[j][1]);
                mma16816(acc[0][2 * j + 1], ah0, bm[j][2], bm[j][3]);
                mma16816(acc[1][2 * j],     ah1, bm[j][0], bm[j][1]);
                mma16816(acc[1][2 * j + 1], ah1, bm[j][2], bm[j][3]);
            }
        }

        if (c < 7) {
            CP_WAIT0();             // chunk c+1 fills complete (overlapped)
            __syncthreads();        // ONE barrier: publishes A(c+1)+B(c+1)
        }
    }

    // ---- epilogue: score = Sv - 2 * sum(v * 1/(e^{2x}+1)) ----------------
    float qc[8][2], vv[8][2];
    float Sv = 0.f;
#pragma unroll
    for (int j = 0; j < 8; j++) {
        const int c = n0 + nw * 64 + j * 8 + 2 * (lid & 3);
        float2 q2 = *(const float2*)(g_q + b * 512 + c);
        float2 v2 = *(const float2*)(v + c);
        qc[j][0] = q2.x * TANH_C;
        qc[j][1] = q2.y * TANH_C;
        vv[j][0] = v2.x;
        vv[j][1] = v2.y;
        Sv += v2.x + v2.y;
    }

    float part[2][2] = {{0.f, 0.f}, {0.f, 0.f}};
#pragma unroll
    for (int mg = 0; mg < 2; mg++) {
#pragma unroll
        for (int j = 0; j < 8; j++) {
            part[mg][0] = fmaf(vv[j][0], sig_rcp(acc[mg][j][0], qc[j][0]), part[mg][0]);
            part[mg][0] = fmaf(vv[j][1], sig_rcp(acc[mg][j][1], qc[j][1]), part[mg][0]);
            part[mg][1] = fmaf(vv[j][0], sig_rcp(acc[mg][j][2], qc[j][0]), part[mg][1]);
            part[mg][1] = fmaf(vv[j][1], sig_rcp(acc[mg][j][3], qc[j][1]), part[mg][1]);
        }
    }

    float* red = (float*)(sm + OFF_RED);   // [2 nw][128 rows]
    __syncthreads();
#pragma unroll
    for (int mg = 0; mg < 2; mg++)
#pragma unroll
        for (int hf = 0; hf < 2; hf++) {
            float p = fmaf(-2.0f, part[mg][hf], Sv);
            p += __shfl_xor_sync(0xffffffffu, p, 1);
            p += __shfl_xor_sync(0xffffffffu, p, 2);
            if ((lid & 3) == 0)
                red[nw * 128 + mw * 32 + mg * 16 + hf * 8 + (lid >> 2)] = p;
        }
    __syncthreads();
    if (t < 128) {
        float p = red[t] + red[128 + t];
        atomicAdd(&g_scores[b * SS + mtile * 128 + t], p);
    }
}

// ---------------------------------------------------------------------------
// Softmax over S per batch row (applies mask here)
// ---------------------------------------------------------------------------
__global__ void softmax_kernel(const int* __restrict__ mask,
                               float* __restrict__ out_attn) {
    const int b = blockIdx.x;
    const int t = threadIdx.x;   // 256
    __shared__ float red[256];
    const float* sc = g_scores + b * SS;
    const int* mk = mask + b * SS;

    float vals[16];
    float m = -INFINITY;
#pragma unroll
    for (int i = 0; i < 16; i++) {
        int s = t + i * 256;
        vals[i] = (mk[s] != 0) ? -1e9f : sc[s];
        m = fmaxf(m, vals[i]);
    }
    red[t] = m;
    __syncthreads();
    for (int o = 128; o > 0; o >>= 1) {
        if (t < o) red[t] = fmaxf(red[t], red[t + o]);
        __syncthreads();
    }
    m = red[0];
    __syncthreads();

    float sum = 0.f;
#pragma unroll
    for (int i = 0; i < 16; i++) {
        vals[i] = expf(vals[i] - m);
        sum += vals[i];
    }
    red[t] = sum;
    __syncthreads();
    for (int o = 128; o > 0; o >>= 1) {
        if (t < o) red[t] += red[t + o];
        __syncthreads();
    }
    const float inv = 1.f / red[0];
#pragma unroll
    for (int i = 0; i < 16; i++)
        out_attn[b * SS + t + i * 256] = vals[i] * inv;
}

// ---------------------------------------------------------------------------
// ctx[b,e] = sum_s attn[b,s] * enc[b,s,e]   (grid 64 x 32, 64-token chunks)
// ---------------------------------------------------------------------------
__global__ void ctx_kernel(const float* __restrict__ enc_out,
                           const float* __restrict__ attn,
                           float* __restrict__ ctx) {
    const int b = blockIdx.y;
    const int sch = blockIdx.x;
    const int e4 = threadIdx.x * 4;
    const float* ap = attn + b * SS + sch * 64;
    const float* ep = enc_out + ((size_t)b * SS + (size_t)sch * 64) * 512 + e4;

    float4 acc0 = make_float4(0.f, 0.f, 0.f, 0.f);
    float4 acc1 = make_float4(0.f, 0.f, 0.f, 0.f);
#pragma unroll 8
    for (int s = 0; s < 64; s += 2) {
        float a0 = __ldg(&ap[s]);
        float a1 = __ldg(&ap[s + 1]);
        float4 x0 = *(const float4*)(ep + (size_t)s * 512);
        float4 x1 = *(const float4*)(ep + (size_t)(s + 1) * 512);
        acc0.x = fmaf(a0, x0.x, acc0.x);
        acc0.y = fmaf(a0, x0.y, acc0.y);
        acc0.z = fmaf(a0, x0.z, acc0.z);
        acc0.w = fmaf(a0, x0.w, acc0.w);
        acc1.x = fmaf(a1, x1.x, acc1.x);
        acc1.y = fmaf(a1, x1.y, acc1.y);
        acc1.z = fmaf(a1, x1.z, acc1.z);
        acc1.w = fmaf(a1, x1.w, acc1.w);
    }
    atomicAdd(&ctx[b * 512 + e4 + 0], acc0.x + acc1.x);
    atomicAdd(&ctx[b * 512 + e4 + 1], acc0.y + acc1.y);
    atomicAdd(&ctx[b * 512 + e4 + 2], acc0.z + acc1.z);
    atomicAdd(&ctx[b * 512 + e4 + 3], acc0.w + acc1.w);
}

// ---------------------------------------------------------------------------
extern "C" void kernel_launch(void* const* d_in, const int* in_sizes, int n_in,
                              void* d_out, int out_size) {
    const float* h    = (const float*)d_in[0];
    const float* enc  = (const float*)d_in[1];
    const int*   mask = (const int*)d_in[2];
    const float* W_h  = (const float*)d_in[3];
    const float* W_s  = (const float*)d_in[4];
    const float* v    = (const float*)d_in[5];

    float* out  = (float*)d_out;
    float* ctx  = out;                 // [32, 512]
    float* attn = out + BB * 512;      // [32, 4096]

    static int attr_done = 0;
    if (!attr_done) {
        cudaFuncSetAttribute(score_mma_kernel,
                             cudaFuncAttributeMaxDynamicSharedMemorySize, SMEM_DYN);
        attr_done = 1;
    }

    cudaMemsetAsync(ctx, 0, BB * 512 * sizeof(float));
    prep_kernel<<<33376, 512>>>(W_s, h, W_h, enc);
    score_mma_kernel<<<dim3(4, 32, 32), 256, SMEM_DYN>>>(v);
    softmax_kernel<<<BB, 256>>>(mask, attn);
    ctx_kernel<<<dim3(64, 32), 128>>>(enc, attn, ctx);
}